// round 1
// baseline (speedup 1.0000x reference)
#include <cuda_runtime.h>
#include <cuda_bf16.h>
#include <math.h>

// Problem constants
#define BB   2
#define SS   2048
#define DD   4096
#define QH   32
#define KVH  8
#define HD   128
#define KVD  (KVH*HD)      // 1024
#define GROUP (QH/KVH)     // 4
#define TOK  (BB*SS)       // 4096

// Scratch (no cudaMalloc allowed)
__device__ float g_q[TOK*DD];     // q after proj+rope  [B,S,QH,HD]
__device__ float g_k[TOK*KVD];    // k                  [B,S,KVH,HD]
__device__ float g_v[TOK*KVD];    // v                  [B,S,KVH,HD]
__device__ float g_ctx[TOK*DD];   // attention output   [B,S,QH,HD]

// ---------------------------------------------------------------------------
// SGEMM: C[M,N] = A[M,K] @ W[N,K]^T + bias    (both A and W row-major, K-major)
// 128x128 tile, BK=16, 256 threads, 8x8 per thread.
// ---------------------------------------------------------------------------
#define GBM 128
#define GBN 128
#define GBK 16

__global__ __launch_bounds__(256) void sgemm_tn(
    const float* __restrict__ A, const float* __restrict__ W,
    const float* __restrict__ bias, float* __restrict__ C,
    int M, int N, int K)
{
    __shared__ float As[GBK][GBM + 4];
    __shared__ float Bs[GBK][GBN + 4];

    const int t  = threadIdx.x;
    const int tx = t & 15;
    const int ty = t >> 4;
    const int m0 = blockIdx.y * GBM;
    const int n0 = blockIdx.x * GBN;

    const float* Aptr = A + (size_t)m0 * K;
    const float* Wptr = W + (size_t)n0 * K;

    float acc[8][8];
#pragma unroll
    for (int i = 0; i < 8; i++)
#pragma unroll
        for (int j = 0; j < 8; j++) acc[i][j] = 0.f;

    for (int k0 = 0; k0 < K; k0 += GBK) {
#pragma unroll
        for (int u = 0; u < 2; u++) {
            int id  = t + u * 256;        // 0..511 float4 ids
            int row = id >> 2;            // 0..127
            int c4  = id & 3;             // 0..3
            float4 va = *(const float4*)(Aptr + (size_t)row * K + k0 + c4 * 4);
            As[c4*4+0][row] = va.x; As[c4*4+1][row] = va.y;
            As[c4*4+2][row] = va.z; As[c4*4+3][row] = va.w;
            float4 vb = *(const float4*)(Wptr + (size_t)row * K + k0 + c4 * 4);
            Bs[c4*4+0][row] = vb.x; Bs[c4*4+1][row] = vb.y;
            Bs[c4*4+2][row] = vb.z; Bs[c4*4+3][row] = vb.w;
        }
        __syncthreads();

#pragma unroll
        for (int kk = 0; kk < GBK; kk++) {
            float a[8], b[8];
            *(float4*)(&a[0]) = *(const float4*)(&As[kk][ty*4]);
            *(float4*)(&a[4]) = *(const float4*)(&As[kk][64 + ty*4]);
            *(float4*)(&b[0]) = *(const float4*)(&Bs[kk][tx*4]);
            *(float4*)(&b[4]) = *(const float4*)(&Bs[kk][64 + tx*4]);
#pragma unroll
            for (int i = 0; i < 8; i++)
#pragma unroll
                for (int j = 0; j < 8; j++)
                    acc[i][j] += a[i] * b[j];
        }
        __syncthreads();
    }

    // epilogue with bias
    float bv[8];
#pragma unroll
    for (int j = 0; j < 4; j++) {
        bv[j]     = bias[n0 + tx*4 + j];
        bv[4 + j] = bias[n0 + 64 + tx*4 + j];
    }
#pragma unroll
    for (int i = 0; i < 8; i++) {
        int r = m0 + ((i < 4) ? (ty*4 + i) : (64 + ty*4 + i - 4));
        float4 o1 = make_float4(acc[i][0]+bv[0], acc[i][1]+bv[1],
                                acc[i][2]+bv[2], acc[i][3]+bv[3]);
        float4 o2 = make_float4(acc[i][4]+bv[4], acc[i][5]+bv[5],
                                acc[i][6]+bv[6], acc[i][7]+bv[7]);
        *(float4*)(C + (size_t)r * N + n0 + tx*4)      = o1;
        *(float4*)(C + (size_t)r * N + n0 + 64 + tx*4) = o2;
    }
}

// ---------------------------------------------------------------------------
// RoPE (in place) over x laid out [B, S, nheads, HD]; one thread per (.., pair)
// ---------------------------------------------------------------------------
__global__ void rope_kernel(float* __restrict__ x, const float* __restrict__ fc,
                            const int* __restrict__ startpos, int nheads, int npairs)
{
    int idx = blockIdx.x * blockDim.x + threadIdx.x;
    if (idx >= npairs) return;
    int p = idx & 63;                       // HD/2 = 64
    int s = (idx >> 6) / nheads;            // token within [B*S)
    s = s % SS;                             // sequence position
    int s_abs = startpos[0] + s;
    float2 cs = *(const float2*)(fc + ((size_t)s_abs * 64 + p) * 2);
    float2 v  = *(float2*)(x + (size_t)idx * 2);
    float2 r;
    r.x = v.x * cs.x - v.y * cs.y;
    r.y = v.x * cs.y + v.y * cs.x;
    *(float2*)(x + (size_t)idx * 2) = r;
}

// ---------------------------------------------------------------------------
// Causal flash attention, fp32. BM=BN=64, 256 threads.
// Thread map: tx = t%16 (score cols / out cols), ty = t/16 (rows).
// Score tile 4x4 per thread; output tile 4 rows x 8 cols per thread.
// Shared: Qs[64][128], Ks[64][129], Vs[64][128], Ps[64][64]
// ---------------------------------------------------------------------------
#define ATT_SMEM_FLOATS (64*128 + 64*129 + 64*128 + 64*64)
#define ATT_SMEM_BYTES  (ATT_SMEM_FLOATS * 4)

__global__ __launch_bounds__(256) void attn_kernel(
    const float* __restrict__ q, const float* __restrict__ k,
    const float* __restrict__ v, float* __restrict__ ctx)
{
    extern __shared__ float sh[];
    float* Qs = sh;                   // 64*128
    float* Ks = sh + 64*128;          // 64*129
    float* Vs = Ks + 64*129;          // 64*128
    float* Ps = Vs + 64*128;          // 64*64

    const int b   = blockIdx.z;
    const int h   = blockIdx.y;        // 0..31
    const int kvh = h / GROUP;
    const int m0  = blockIdx.x * 64;

    const int t  = threadIdx.x;
    const int tx = t & 15;
    const int ty = t >> 4;

    const float scale = 0.08838834764831845f;  // 1/sqrt(128)

    const float* qbase = q   + ((size_t)b * SS * QH  + h)   * HD;
    const float* kbase = k   + ((size_t)b * SS * KVH + kvh) * HD;
    const float* vbase = v   + ((size_t)b * SS * KVH + kvh) * HD;
    float*       cbase = ctx + ((size_t)b * SS * QH  + h)   * HD;

    // load Q tile (rows m0..m0+63), row stride QH*HD = 4096
#pragma unroll
    for (int u = 0; u < 8; u++) {
        int id  = t + u * 256;      // 0..2047 float4 ids
        int row = id >> 5;
        int c4  = id & 31;
        float4 vq = *(const float4*)(qbase + (size_t)(m0 + row) * (QH*HD) + c4 * 4);
        *(float4*)&Qs[row * 128 + c4 * 4] = vq;
    }

    float mrow[4], lrow[4], o[4][8];
#pragma unroll
    for (int i = 0; i < 4; i++) {
        mrow[i] = -INFINITY; lrow[i] = 0.f;
#pragma unroll
        for (int c = 0; c < 8; c++) o[i][c] = 0.f;
    }

    const int ntiles = (m0 >> 6) + 1;

    for (int tile = 0; tile < ntiles; tile++) {
        const int n0 = tile * 64;
        // load K (stride-129 rows) and V (stride-128) tiles; row stride KVH*HD=1024
#pragma unroll
        for (int u = 0; u < 8; u++) {
            int id  = t + u * 256;
            int row = id >> 5;
            int c4  = id & 31;
            float4 kv = *(const float4*)(kbase + (size_t)(n0 + row) * (KVH*HD) + c4 * 4);
            int ko = row * 129 + c4 * 4;
            Ks[ko] = kv.x; Ks[ko+1] = kv.y; Ks[ko+2] = kv.z; Ks[ko+3] = kv.w;
            float4 vv = *(const float4*)(vbase + (size_t)(n0 + row) * (KVH*HD) + c4 * 4);
            *(float4*)&Vs[row * 128 + c4 * 4] = vv;
        }
        __syncthreads();

        // scores S = Q K^T
        float sc[4][4];
#pragma unroll
        for (int i = 0; i < 4; i++)
#pragma unroll
            for (int j = 0; j < 4; j++) sc[i][j] = 0.f;

#pragma unroll 4
        for (int d = 0; d < 128; d++) {
            float qd[4], kd[4];
#pragma unroll
            for (int i = 0; i < 4; i++) qd[i] = Qs[(ty*4 + i) * 128 + d];
#pragma unroll
            for (int j = 0; j < 4; j++) kd[j] = Ks[(tx*4 + j) * 129 + d];
#pragma unroll
            for (int i = 0; i < 4; i++)
#pragma unroll
                for (int j = 0; j < 4; j++)
                    sc[i][j] += qd[i] * kd[j];
        }

#pragma unroll
        for (int i = 0; i < 4; i++)
#pragma unroll
            for (int j = 0; j < 4; j++) sc[i][j] *= scale;

        if (n0 == m0) {  // diagonal tile: mask cols > rows (relative indices)
#pragma unroll
            for (int i = 0; i < 4; i++)
#pragma unroll
                for (int j = 0; j < 4; j++)
                    if ((tx*4 + j) > (ty*4 + i)) sc[i][j] = -INFINITY;
        }

        // row max across this tile
        float rmax[4];
#pragma unroll
        for (int i = 0; i < 4; i++)
            rmax[i] = fmaxf(fmaxf(sc[i][0], sc[i][1]), fmaxf(sc[i][2], sc[i][3]));
#pragma unroll
        for (int msk = 1; msk < 16; msk <<= 1)
#pragma unroll
            for (int i = 0; i < 4; i++)
                rmax[i] = fmaxf(rmax[i], __shfl_xor_sync(0xffffffffu, rmax[i], msk));

        float rsum[4];
#pragma unroll
        for (int i = 0; i < 4; i++) {
            float mnew = fmaxf(mrow[i], rmax[i]);
            float corr = __expf(mrow[i] - mnew);
            mrow[i] = mnew;
            float s0 = 0.f;
#pragma unroll
            for (int j = 0; j < 4; j++) {
                float p = __expf(sc[i][j] - mnew);
                Ps[(ty*4 + i) * 64 + tx*4 + j] = p;
                s0 += p;
            }
            rsum[i] = s0;
            lrow[i] *= corr;
#pragma unroll
            for (int c = 0; c < 8; c++) o[i][c] *= corr;
        }
#pragma unroll
        for (int msk = 1; msk < 16; msk <<= 1)
#pragma unroll
            for (int i = 0; i < 4; i++)
                rsum[i] += __shfl_xor_sync(0xffffffffu, rsum[i], msk);
#pragma unroll
        for (int i = 0; i < 4; i++) lrow[i] += rsum[i];

        __syncwarp();   // Ps row-group is produced & consumed within the same warp

        // O += P @ V
#pragma unroll 4
        for (int j = 0; j < 64; j++) {
            float pv[4];
#pragma unroll
            for (int i = 0; i < 4; i++) pv[i] = Ps[(ty*4 + i) * 64 + j];
            float4 v1 = *(const float4*)&Vs[j * 128 + tx*4];
            float4 v2 = *(const float4*)&Vs[j * 128 + 64 + tx*4];
#pragma unroll
            for (int i = 0; i < 4; i++) {
                o[i][0] += pv[i] * v1.x; o[i][1] += pv[i] * v1.y;
                o[i][2] += pv[i] * v1.z; o[i][3] += pv[i] * v1.w;
                o[i][4] += pv[i] * v2.x; o[i][5] += pv[i] * v2.y;
                o[i][6] += pv[i] * v2.z; o[i][7] += pv[i] * v2.w;
            }
        }
        __syncthreads();  // Vs/Ks consumed; safe to overwrite next tile
    }

    // finalize and store ctx[b, m0+r, h, :]
#pragma unroll
    for (int i = 0; i < 4; i++) {
        float inv = 1.0f / lrow[i];
        int r = m0 + ty*4 + i;
        float4 w1 = make_float4(o[i][0]*inv, o[i][1]*inv, o[i][2]*inv, o[i][3]*inv);
        float4 w2 = make_float4(o[i][4]*inv, o[i][5]*inv, o[i][6]*inv, o[i][7]*inv);
        *(float4*)(cbase + (size_t)r * (QH*HD) + tx*4)      = w1;
        *(float4*)(cbase + (size_t)r * (QH*HD) + 64 + tx*4) = w2;
    }
}

// ---------------------------------------------------------------------------
// launch
// ---------------------------------------------------------------------------
extern "C" void kernel_launch(void* const* d_in, const int* in_sizes, int n_in,
                              void* d_out, int out_size)
{
    const float* xs   = (const float*)d_in[0];
    const int*   spos = (const int*)  d_in[1];
    const float* fc   = (const float*)d_in[2];
    const float* Wq   = (const float*)d_in[3];
    const float* bq   = (const float*)d_in[4];
    const float* Wk   = (const float*)d_in[5];
    const float* bk   = (const float*)d_in[6];
    const float* Wv   = (const float*)d_in[7];
    const float* bv   = (const float*)d_in[8];
    const float* Wo   = (const float*)d_in[9];
    const float* bo   = (const float*)d_in[10];
    float* out = (float*)d_out;

    float *qp, *kp, *vp, *cp;
    cudaGetSymbolAddress((void**)&qp, g_q);
    cudaGetSymbolAddress((void**)&kp, g_k);
    cudaGetSymbolAddress((void**)&vp, g_v);
    cudaGetSymbolAddress((void**)&cp, g_ctx);

    cudaFuncSetAttribute(attn_kernel,
                         cudaFuncAttributeMaxDynamicSharedMemorySize,
                         ATT_SMEM_BYTES);

    // QKV projections
    sgemm_tn<<<dim3(DD/GBN,  TOK/GBM), 256>>>(xs, Wq, bq, qp, TOK, DD,  DD);
    sgemm_tn<<<dim3(KVD/GBN, TOK/GBM), 256>>>(xs, Wk, bk, kp, TOK, KVD, DD);
    sgemm_tn<<<dim3(KVD/GBN, TOK/GBM), 256>>>(xs, Wv, bv, vp, TOK, KVD, DD);

    // RoPE on q and k
    {
        int npq = TOK * QH * (HD/2);    // 8,388,608
        int npk = TOK * KVH * (HD/2);   // 2,097,152
        rope_kernel<<<(npq + 255)/256, 256>>>(qp, fc, spos, QH,  npq);
        rope_kernel<<<(npk + 255)/256, 256>>>(kp, fc, spos, KVH, npk);
    }

    // attention
    attn_kernel<<<dim3(SS/64, QH, BB), 256, ATT_SMEM_BYTES>>>(qp, kp, vp, cp);

    // output projection
    sgemm_tn<<<dim3(DD/GBN, TOK/GBM), 256>>>(cp, Wo, bo, out, TOK, DD, DD);
}

// round 3
// speedup vs baseline: 1.5936x; 1.5936x over previous
#include <cuda_runtime.h>
#include <cuda_bf16.h>
#include <math.h>
#include <stdint.h>

// Problem constants
#define BB   2
#define SS   2048
#define DD   4096
#define QH   32
#define KVH  8
#define HD   128
#define KVD  (KVH*HD)      // 1024
#define GROUP (QH/KVH)     // 4
#define TOK  (BB*SS)       // 4096
#define K3   (3*DD)        // 12288: [hi | lo | hi] / [hi | hi | lo]

// ---------------------------------------------------------------------------
// Scratch (no cudaMalloc allowed)
// ---------------------------------------------------------------------------
__device__ __align__(16) float g_q[TOK*DD];
__device__ __align__(16) float g_k[TOK*KVD];
__device__ __align__(16) float g_v[TOK*KVD];
__device__ __align__(16) float g_ctx[TOK*DD];

__device__ __align__(16) __nv_bfloat16 g_xc [TOK*K3];   // x   split (A-form)
__device__ __align__(16) __nv_bfloat16 g_wqc[DD*K3];    // Wq  split (B-form)
__device__ __align__(16) __nv_bfloat16 g_wkc[KVD*K3];   // Wk  split (B-form)
__device__ __align__(16) __nv_bfloat16 g_wvc[KVD*K3];   // Wv  split (B-form)
__device__ __align__(16) __nv_bfloat16 g_woc[DD*K3];    // Wo  split (B-form)
__device__ __align__(16) __nv_bfloat16 g_cc [TOK*K3];   // ctx split (A-form)

// ---------------------------------------------------------------------------
// helpers
// ---------------------------------------------------------------------------
__device__ __forceinline__ uint32_t smem_u32(const void* p) {
    uint32_t a;
    asm("{ .reg .u64 t; cvta.to.shared.u64 t, %1; cvt.u32.u64 %0, t; }" : "=r"(a) : "l"(p));
    return a;
}

#define CP_ASYNC16(dst, src) \
    asm volatile("cp.async.cg.shared.global [%0], [%1], 16;" :: "r"(dst), "l"(src))
#define CP_COMMIT()   asm volatile("cp.async.commit_group;" ::: "memory")
#define CP_WAIT(n)    asm volatile("cp.async.wait_group %0;" :: "n"(n) : "memory")

#define LDM_X4(r0, r1, r2, r3, addr) \
    asm volatile("ldmatrix.sync.aligned.m8n8.x4.shared.b16 {%0,%1,%2,%3}, [%4];" \
        : "=r"(r0), "=r"(r1), "=r"(r2), "=r"(r3) : "r"(addr))

#define MMA16816(d, a, b) \
    asm volatile("mma.sync.aligned.m16n8k16.row.col.f32.bf16.bf16.f32 " \
        "{%0,%1,%2,%3},{%4,%5,%6,%7},{%8,%9},{%0,%1,%2,%3};" \
        : "+f"((d)[0]), "+f"((d)[1]), "+f"((d)[2]), "+f"((d)[3]) \
        : "r"((a)[0]), "r"((a)[1]), "r"((a)[2]), "r"((a)[3]), \
          "r"((b)[0]), "r"((b)[1]))

// ---------------------------------------------------------------------------
// fp32 -> 3-term bf16 split.
// mode 0 (A-form): out row = [hi | lo | hi]
// mode 1 (B-form): out row = [hi | hi | lo]
// so that dot(A', B') = hi*hi + lo*hi + hi*lo  (only lo*lo ~2^-18 dropped)
// ---------------------------------------------------------------------------
__global__ void split_bf16_kernel(const float* __restrict__ in,
                                  __nv_bfloat16* __restrict__ out,
                                  int K, int total4, int mode)
{
    int idx = blockIdx.x * blockDim.x + threadIdx.x;
    if (idx >= total4) return;
    float4 v = ((const float4*)in)[idx];
    int K4 = K >> 2;
    int r  = idx / K4;
    int k  = (idx - r * K4) << 2;
    float vv[4] = {v.x, v.y, v.z, v.w};
    __nv_bfloat16 h[4], l[4];
#pragma unroll
    for (int i = 0; i < 4; i++) {
        h[i] = __float2bfloat16(vv[i]);
        l[i] = __float2bfloat16(vv[i] - __bfloat162float(h[i]));
    }
    __nv_bfloat16* row = out + (size_t)r * (3*K);
    if (mode == 0) {
        *(uint2*)(row + k)       = *(uint2*)h;
        *(uint2*)(row + K + k)   = *(uint2*)l;
        *(uint2*)(row + 2*K + k) = *(uint2*)h;
    } else {
        *(uint2*)(row + k)       = *(uint2*)h;
        *(uint2*)(row + K + k)   = *(uint2*)h;
        *(uint2*)(row + 2*K + k) = *(uint2*)l;
    }
}

// ---------------------------------------------------------------------------
// bf16 MMA GEMM: C[M,N] = A[M,K3] @ B[N,K3]^T + bias
// CTA 128x128, BK=32, 256 threads (8 warps, 2x4), 4-stage cp.async pipeline.
// ---------------------------------------------------------------------------
#define CTM   128
#define CTN   128
#define GBK   32
#define NST   4
#define NCH   (K3 / GBK)          // 384
#define ROWB  80                  // smem row stride in bytes (32 bf16 + 8 pad)
#define ATILE (CTM * ROWB)        // 10240 B
#define BTILE (CTN * ROWB)        // 10240 B
#define STAGE (ATILE + BTILE)     // 20480 B
#define GSMEM (NST * STAGE)       // 81920 B

__global__ __launch_bounds__(256, 2) void gemm_mma(
    const __nv_bfloat16* __restrict__ A, const __nv_bfloat16* __restrict__ B,
    const float* __restrict__ bias, float* __restrict__ C, int N)
{
    extern __shared__ char smraw[];
    const int t    = threadIdx.x;
    const int lane = t & 31;
    const int wid  = t >> 5;
    const int wm   = wid & 1;           // 0..1  (M)
    const int wn   = wid >> 1;          // 0..3  (N)
    const int m0   = blockIdx.x * CTM;
    const int n0   = blockIdx.y * CTN;
    const uint32_t sb = smem_u32(smraw);

    float acc[4][4][4];
#pragma unroll
    for (int i = 0; i < 4; i++)
#pragma unroll
        for (int j = 0; j < 4; j++)
#pragma unroll
            for (int r = 0; r < 4; r++) acc[i][j][r] = 0.f;

    // per-thread load indices (two 16B chunks of A, two of B per stage)
    const int row0 = t >> 1;                 // with chunk pairing below
    // chunk id layout: id in [0,512): row=id>>2, c=id&3 ; thread handles id=t, t+256
    // precompute global row pointers
    const __nv_bfloat16* Ag0 = A + (size_t)(m0 + (t >> 2)) * K3 + (t & 3) * 8;
    const __nv_bfloat16* Ag1 = A + (size_t)(m0 + ((t + 256) >> 2)) * K3 + (t & 3) * 8;
    const __nv_bfloat16* Bg0 = B + (size_t)(n0 + (t >> 2)) * K3 + (t & 3) * 8;
    const __nv_bfloat16* Bg1 = B + (size_t)(n0 + ((t + 256) >> 2)) * K3 + (t & 3) * 8;
    const uint32_t sA0 = (t >> 2) * ROWB + (t & 3) * 16;
    const uint32_t sA1 = ((t + 256) >> 2) * ROWB + (t & 3) * 16;
    (void)row0;

#define LOAD_STAGE(st, k0) do {                                        \
    uint32_t ab = sb + (st) * STAGE;                                   \
    uint32_t bb = ab + ATILE;                                          \
    CP_ASYNC16(ab + sA0, Ag0 + (k0));                                  \
    CP_ASYNC16(ab + sA1, Ag1 + (k0));                                  \
    CP_ASYNC16(bb + sA0, Bg0 + (k0));                                  \
    CP_ASYNC16(bb + sA1, Bg1 + (k0));                                  \
} while (0)

    // prologue: stages 0..2
#pragma unroll
    for (int s = 0; s < NST - 1; s++) {
        LOAD_STAGE(s, s * GBK);
        CP_COMMIT();
    }

    // ldmatrix base offsets (per warp, per ks recomputed cheaply)
    const uint32_t aoffs = (wm * 64 + (lane & 15)) * ROWB + ((lane >> 4) << 4);
    const uint32_t boffs = (wn * 32 + (lane & 15)) * ROWB + ((lane >> 4) << 4);

    for (int c = 0; c < NCH; c++) {
        const int st = c & (NST - 1);
        CP_WAIT(2);
        __syncthreads();
        if (c + NST - 1 < NCH) LOAD_STAGE((c + NST - 1) & (NST - 1), (c + NST - 1) * GBK);
        CP_COMMIT();

        const uint32_t ab = sb + st * STAGE;
        const uint32_t bb = ab + ATILE;

#pragma unroll
        for (int ks = 0; ks < 2; ks++) {
            uint32_t a[4][4];
            uint32_t bf[4][2];
#pragma unroll
            for (int mi = 0; mi < 4; mi++)
                LDM_X4(a[mi][0], a[mi][1], a[mi][2], a[mi][3],
                       ab + aoffs + mi * 16 * ROWB + ks * 32);
#pragma unroll
            for (int p = 0; p < 2; p++) {
                uint32_t r0, r1, r2, r3;
                LDM_X4(r0, r1, r2, r3, bb + boffs + p * 16 * ROWB + ks * 32);
                bf[2*p][0]   = r0; bf[2*p][1]   = r2;
                bf[2*p+1][0] = r1; bf[2*p+1][1] = r3;
            }
#pragma unroll
            for (int mi = 0; mi < 4; mi++)
#pragma unroll
                for (int ni = 0; ni < 4; ni++)
                    MMA16816(acc[mi][ni], a[mi], bf[ni]);
        }
    }

    // epilogue: bias + store
#pragma unroll
    for (int mi = 0; mi < 4; mi++) {
        int r0 = m0 + wm * 64 + mi * 16 + (lane >> 2);
#pragma unroll
        for (int ni = 0; ni < 4; ni++) {
            int col = n0 + wn * 32 + ni * 8 + (lane & 3) * 2;
            float2 bv = *(const float2*)(bias + col);
            float2 o0 = make_float2(acc[mi][ni][0] + bv.x, acc[mi][ni][1] + bv.y);
            float2 o1 = make_float2(acc[mi][ni][2] + bv.x, acc[mi][ni][3] + bv.y);
            *(float2*)(C + (size_t)r0 * N + col)       = o0;
            *(float2*)(C + (size_t)(r0 + 8) * N + col) = o1;
        }
    }
#undef LOAD_STAGE
}

// ---------------------------------------------------------------------------
// RoPE (in place) over x laid out [B, S, nheads, HD]
// ---------------------------------------------------------------------------
__global__ void rope_kernel(float* __restrict__ x, const float* __restrict__ fc,
                            const int* __restrict__ startpos, int nheads, int npairs)
{
    int idx = blockIdx.x * blockDim.x + threadIdx.x;
    if (idx >= npairs) return;
    int p = idx & 63;
    int s = (idx >> 6) / nheads;
    s = s % SS;
    int s_abs = startpos[0] + s;
    float2 cs = *(const float2*)(fc + ((size_t)s_abs * 64 + p) * 2);
    float2 v  = *(float2*)(x + (size_t)idx * 2);
    float2 r;
    r.x = v.x * cs.x - v.y * cs.y;
    r.y = v.x * cs.y + v.y * cs.x;
    *(float2*)(x + (size_t)idx * 2) = r;
}

// ---------------------------------------------------------------------------
// Causal flash attention, fp32 (same structure as R1-passing version)
// ---------------------------------------------------------------------------
#define ATT_SMEM_FLOATS (64*128 + 64*129 + 64*128 + 64*64)
#define ATT_SMEM_BYTES  (ATT_SMEM_FLOATS * 4)

__global__ __launch_bounds__(256) void attn_kernel(
    const float* __restrict__ q, const float* __restrict__ k,
    const float* __restrict__ v, float* __restrict__ ctx)
{
    extern __shared__ float sh[];
    float* Qs = sh;
    float* Ks = sh + 64*128;
    float* Vs = Ks + 64*129;
    float* Ps = Vs + 64*128;

    const int b   = blockIdx.z;
    const int h   = blockIdx.y;
    const int kvh = h / GROUP;
    const int m0  = blockIdx.x * 64;

    const int t  = threadIdx.x;
    const int tx = t & 15;
    const int ty = t >> 4;

    const float scale = 0.08838834764831845f;

    const float* qbase = q   + ((size_t)b * SS * QH  + h)   * HD;
    const float* kbase = k   + ((size_t)b * SS * KVH + kvh) * HD;
    const float* vbase = v   + ((size_t)b * SS * KVH + kvh) * HD;
    float*       cbase = ctx + ((size_t)b * SS * QH  + h)   * HD;

#pragma unroll
    for (int u = 0; u < 8; u++) {
        int id  = t + u * 256;
        int row = id >> 5;
        int c4  = id & 31;
        float4 vq = *(const float4*)(qbase + (size_t)(m0 + row) * (QH*HD) + c4 * 4);
        *(float4*)&Qs[row * 128 + c4 * 4] = vq;
    }

    float mrow[4], lrow[4], o[4][8];
#pragma unroll
    for (int i = 0; i < 4; i++) {
        mrow[i] = -INFINITY; lrow[i] = 0.f;
#pragma unroll
        for (int c = 0; c < 8; c++) o[i][c] = 0.f;
    }

    const int ntiles = (m0 >> 6) + 1;

    for (int tile = 0; tile < ntiles; tile++) {
        const int n0 = tile * 64;
#pragma unroll
        for (int u = 0; u < 8; u++) {
            int id  = t + u * 256;
            int row = id >> 5;
            int c4  = id & 31;
            float4 kv = *(const float4*)(kbase + (size_t)(n0 + row) * (KVH*HD) + c4 * 4);
            int ko = row * 129 + c4 * 4;
            Ks[ko] = kv.x; Ks[ko+1] = kv.y; Ks[ko+2] = kv.z; Ks[ko+3] = kv.w;
            float4 vv = *(const float4*)(vbase + (size_t)(n0 + row) * (KVH*HD) + c4 * 4);
            *(float4*)&Vs[row * 128 + c4 * 4] = vv;
        }
        __syncthreads();

        float sc[4][4];
#pragma unroll
        for (int i = 0; i < 4; i++)
#pragma unroll
            for (int j = 0; j < 4; j++) sc[i][j] = 0.f;

#pragma unroll 4
        for (int d = 0; d < 128; d++) {
            float qd[4], kd[4];
#pragma unroll
            for (int i = 0; i < 4; i++) qd[i] = Qs[(ty*4 + i) * 128 + d];
#pragma unroll
            for (int j = 0; j < 4; j++) kd[j] = Ks[(tx*4 + j) * 129 + d];
#pragma unroll
            for (int i = 0; i < 4; i++)
#pragma unroll
                for (int j = 0; j < 4; j++)
                    sc[i][j] += qd[i] * kd[j];
        }

#pragma unroll
        for (int i = 0; i < 4; i++)
#pragma unroll
            for (int j = 0; j < 4; j++) sc[i][j] *= scale;

        if (n0 == m0) {
#pragma unroll
            for (int i = 0; i < 4; i++)
#pragma unroll
                for (int j = 0; j < 4; j++)
                    if ((tx*4 + j) > (ty*4 + i)) sc[i][j] = -INFINITY;
        }

        float rmax[4];
#pragma unroll
        for (int i = 0; i < 4; i++)
            rmax[i] = fmaxf(fmaxf(sc[i][0], sc[i][1]), fmaxf(sc[i][2], sc[i][3]));
#pragma unroll
        for (int msk = 1; msk < 16; msk <<= 1)
#pragma unroll
            for (int i = 0; i < 4; i++)
                rmax[i] = fmaxf(rmax[i], __shfl_xor_sync(0xffffffffu, rmax[i], msk));

        float rsum[4];
#pragma unroll
        for (int i = 0; i < 4; i++) {
            float mnew = fmaxf(mrow[i], rmax[i]);
            float corr = __expf(mrow[i] - mnew);
            mrow[i] = mnew;
            float s0 = 0.f;
#pragma unroll
            for (int j = 0; j < 4; j++) {
                float p = __expf(sc[i][j] - mnew);
                Ps[(ty*4 + i) * 64 + tx*4 + j] = p;
                s0 += p;
            }
            rsum[i] = s0;
            lrow[i] *= corr;
#pragma unroll
            for (int c = 0; c < 8; c++) o[i][c] *= corr;
        }
#pragma unroll
        for (int msk = 1; msk < 16; msk <<= 1)
#pragma unroll
            for (int i = 0; i < 4; i++)
                rsum[i] += __shfl_xor_sync(0xffffffffu, rsum[i], msk);
#pragma unroll
        for (int i = 0; i < 4; i++) lrow[i] += rsum[i];

        __syncwarp();

#pragma unroll 4
        for (int j = 0; j < 64; j++) {
            float pv[4];
#pragma unroll
            for (int i = 0; i < 4; i++) pv[i] = Ps[(ty*4 + i) * 64 + j];
            float4 v1 = *(const float4*)&Vs[j * 128 + tx*4];
            float4 v2 = *(const float4*)&Vs[j * 128 + 64 + tx*4];
#pragma unroll
            for (int i = 0; i < 4; i++) {
                o[i][0] += pv[i] * v1.x; o[i][1] += pv[i] * v1.y;
                o[i][2] += pv[i] * v1.z; o[i][3] += pv[i] * v1.w;
                o[i][4] += pv[i] * v2.x; o[i][5] += pv[i] * v2.y;
                o[i][6] += pv[i] * v2.z; o[i][7] += pv[i] * v2.w;
            }
        }
        __syncthreads();
    }

#pragma unroll
    for (int i = 0; i < 4; i++) {
        float inv = 1.0f / lrow[i];
        int r = m0 + ty*4 + i;
        float4 w1 = make_float4(o[i][0]*inv, o[i][1]*inv, o[i][2]*inv, o[i][3]*inv);
        float4 w2 = make_float4(o[i][4]*inv, o[i][5]*inv, o[i][6]*inv, o[i][7]*inv);
        *(float4*)(cbase + (size_t)r * (QH*HD) + tx*4)      = w1;
        *(float4*)(cbase + (size_t)r * (QH*HD) + 64 + tx*4) = w2;
    }
}

// ---------------------------------------------------------------------------
// launch
// ---------------------------------------------------------------------------
extern "C" void kernel_launch(void* const* d_in, const int* in_sizes, int n_in,
                              void* d_out, int out_size)
{
    const float* xs   = (const float*)d_in[0];
    const int*   spos = (const int*)  d_in[1];
    const float* fc   = (const float*)d_in[2];
    const float* Wq   = (const float*)d_in[3];
    const float* bq   = (const float*)d_in[4];
    const float* Wk   = (const float*)d_in[5];
    const float* bk   = (const float*)d_in[6];
    const float* Wv   = (const float*)d_in[7];
    const float* bv   = (const float*)d_in[8];
    const float* Wo   = (const float*)d_in[9];
    const float* bo   = (const float*)d_in[10];
    float* out = (float*)d_out;

    float *qp, *kp, *vp, *cp;
    __nv_bfloat16 *xc, *wqc, *wkc, *wvc, *woc, *cc;
    cudaGetSymbolAddress((void**)&qp,  g_q);
    cudaGetSymbolAddress((void**)&kp,  g_k);
    cudaGetSymbolAddress((void**)&vp,  g_v);
    cudaGetSymbolAddress((void**)&cp,  g_ctx);
    cudaGetSymbolAddress((void**)&xc,  g_xc);
    cudaGetSymbolAddress((void**)&wqc, g_wqc);
    cudaGetSymbolAddress((void**)&wkc, g_wkc);
    cudaGetSymbolAddress((void**)&wvc, g_wvc);
    cudaGetSymbolAddress((void**)&woc, g_woc);
    cudaGetSymbolAddress((void**)&cc,  g_cc);

    cudaFuncSetAttribute(attn_kernel, cudaFuncAttributeMaxDynamicSharedMemorySize,
                         ATT_SMEM_BYTES);
    cudaFuncSetAttribute(gemm_mma, cudaFuncAttributeMaxDynamicSharedMemorySize,
                         GSMEM);

    // split fp32 -> 3-term bf16
    {
        int n;
        n = TOK*DD/4;  split_bf16_kernel<<<(n+255)/256, 256>>>(xs, xc,  DD, n, 0);
        n = DD*DD/4;   split_bf16_kernel<<<(n+255)/256, 256>>>(Wq, wqc, DD, n, 1);
        n = KVD*DD/4;  split_bf16_kernel<<<(n+255)/256, 256>>>(Wk, wkc, DD, n, 1);
        n = KVD*DD/4;  split_bf16_kernel<<<(n+255)/256, 256>>>(Wv, wvc, DD, n, 1);
        n = DD*DD/4;   split_bf16_kernel<<<(n+255)/256, 256>>>(Wo, woc, DD, n, 1);
    }

    // QKV projections on tensor cores
    gemm_mma<<<dim3(TOK/CTM, DD/CTN),  256, GSMEM>>>(xc, wqc, bq, qp, DD);
    gemm_mma<<<dim3(TOK/CTM, KVD/CTN), 256, GSMEM>>>(xc, wkc, bk, kp, KVD);
    gemm_mma<<<dim3(TOK/CTM, KVD/CTN), 256, GSMEM>>>(xc, wvc, bv, vp, KVD);

    // RoPE
    {
        int npq = TOK * QH * (HD/2);
        int npk = TOK * KVH * (HD/2);
        rope_kernel<<<(npq + 255)/256, 256>>>(qp, fc, spos, QH,  npq);
        rope_kernel<<<(npk + 255)/256, 256>>>(kp, fc, spos, KVH, npk);
    }

    // attention (fp32)
    attn_kernel<<<dim3(SS/64, QH, BB), 256, ATT_SMEM_BYTES>>>(qp, kp, vp, cp);

    // split ctx, output projection
    {
        int n = TOK*DD/4;
        split_bf16_kernel<<<(n+255)/256, 256>>>(cp, cc, DD, n, 0);
    }
    gemm_mma<<<dim3(TOK/CTM, DD/CTN), 256, GSMEM>>>(cc, woc, bo, out, DD);
}

// round 4
// speedup vs baseline: 2.1486x; 1.3483x over previous
#include <cuda_runtime.h>
#include <cuda_bf16.h>
#include <math.h>
#include <stdint.h>

// Problem constants
#define BB   2
#define SS   2048
#define DD   4096
#define QH   32
#define KVH  8
#define HD   128
#define KVD  (KVH*HD)      // 1024
#define GROUP (QH/KVH)     // 4
#define TOK  (BB*SS)       // 4096
#define K3   (3*DD)        // 12288

// ---------------------------------------------------------------------------
// Scratch
// ---------------------------------------------------------------------------
__device__ __align__(16) float g_q[TOK*DD];
__device__ __align__(16) float g_k[TOK*KVD];
__device__ __align__(16) float g_v[TOK*KVD];

__device__ __align__(16) __nv_bfloat16 g_xc [TOK*K3];
__device__ __align__(16) __nv_bfloat16 g_wqc[DD*K3];
__device__ __align__(16) __nv_bfloat16 g_wkc[KVD*K3];
__device__ __align__(16) __nv_bfloat16 g_wvc[KVD*K3];
__device__ __align__(16) __nv_bfloat16 g_woc[DD*K3];
__device__ __align__(16) __nv_bfloat16 g_cc [TOK*K3];

__device__ __align__(16) __nv_bfloat16 g_qh[TOK*DD];
__device__ __align__(16) __nv_bfloat16 g_ql[TOK*DD];
__device__ __align__(16) __nv_bfloat16 g_kh[TOK*KVD];
__device__ __align__(16) __nv_bfloat16 g_kl[TOK*KVD];
__device__ __align__(16) __nv_bfloat16 g_vh[TOK*KVD];
__device__ __align__(16) __nv_bfloat16 g_vl[TOK*KVD];

// ---------------------------------------------------------------------------
// helpers
// ---------------------------------------------------------------------------
__device__ __forceinline__ uint32_t smem_u32(const void* p) {
    uint32_t a;
    asm("{ .reg .u64 t; cvta.to.shared.u64 t, %1; cvt.u32.u64 %0, t; }" : "=r"(a) : "l"(p));
    return a;
}

#define CP_ASYNC16(dst, src) \
    asm volatile("cp.async.cg.shared.global [%0], [%1], 16;" :: "r"(dst), "l"(src))
#define CP_COMMIT()   asm volatile("cp.async.commit_group;" ::: "memory")
#define CP_WAIT(n)    asm volatile("cp.async.wait_group %0;" :: "n"(n) : "memory")

#define LDM_X4(r0, r1, r2, r3, addr) \
    asm volatile("ldmatrix.sync.aligned.m8n8.x4.shared.b16 {%0,%1,%2,%3}, [%4];" \
        : "=r"(r0), "=r"(r1), "=r"(r2), "=r"(r3) : "r"(addr))

#define LDM_X4T(r0, r1, r2, r3, addr) \
    asm volatile("ldmatrix.sync.aligned.m8n8.x4.trans.shared.b16 {%0,%1,%2,%3}, [%4];" \
        : "=r"(r0), "=r"(r1), "=r"(r2), "=r"(r3) : "r"(addr))

#define MMA16816(d, a, b) \
    asm volatile("mma.sync.aligned.m16n8k16.row.col.f32.bf16.bf16.f32 " \
        "{%0,%1,%2,%3},{%4,%5,%6,%7},{%8,%9},{%0,%1,%2,%3};" \
        : "+f"((d)[0]), "+f"((d)[1]), "+f"((d)[2]), "+f"((d)[3]) \
        : "r"((a)[0]), "r"((a)[1]), "r"((a)[2]), "r"((a)[3]), \
          "r"((b)[0]), "r"((b)[1]))

// pack two fp32 -> bf16x2 {hi16 = b, lo16 = a}
__device__ __forceinline__ uint32_t pack_bf16(float a, float b) {
    uint32_t d;
    asm("cvt.rn.bf16x2.f32 %0, %1, %2;" : "=r"(d) : "f"(b), "f"(a));
    return d;
}
__device__ __forceinline__ float ex2f(float x) {
    float r; asm("ex2.approx.f32 %0, %1;" : "=f"(r) : "f"(x)); return r;
}

// ---------------------------------------------------------------------------
// fp32 -> 3-term bf16 split (concatenated K form, used for x / weights / ctx)
// mode 0 (A-form): [hi | lo | hi]   mode 1 (B-form): [hi | hi | lo]
// ---------------------------------------------------------------------------
__global__ void split_bf16_kernel(const float* __restrict__ in,
                                  __nv_bfloat16* __restrict__ out,
                                  int K, int total4, int mode)
{
    int idx = blockIdx.x * blockDim.x + threadIdx.x;
    if (idx >= total4) return;
    float4 v = ((const float4*)in)[idx];
    int K4 = K >> 2;
    int r  = idx / K4;
    int k  = (idx - r * K4) << 2;
    float vv[4] = {v.x, v.y, v.z, v.w};
    __nv_bfloat16 h[4], l[4];
#pragma unroll
    for (int i = 0; i < 4; i++) {
        h[i] = __float2bfloat16(vv[i]);
        l[i] = __float2bfloat16(vv[i] - __bfloat162float(h[i]));
    }
    __nv_bfloat16* row = out + (size_t)r * (3*K);
    if (mode == 0) {
        *(uint2*)(row + k)       = *(uint2*)h;
        *(uint2*)(row + K + k)   = *(uint2*)l;
        *(uint2*)(row + 2*K + k) = *(uint2*)h;
    } else {
        *(uint2*)(row + k)       = *(uint2*)h;
        *(uint2*)(row + K + k)   = *(uint2*)h;
        *(uint2*)(row + 2*K + k) = *(uint2*)l;
    }
}

// ---------------------------------------------------------------------------
// rope + hi/lo split for q (with scale) and k.   x: [B,S,nh,HD] fp32
// ---------------------------------------------------------------------------
__global__ void ropesplit_kernel(const float* __restrict__ x,
                                 const float* __restrict__ fc,
                                 const int* __restrict__ startpos,
                                 __nv_bfloat16* __restrict__ oh,
                                 __nv_bfloat16* __restrict__ ol,
                                 int nheads, int total4, float qscale)
{
    int idx = blockIdx.x * blockDim.x + threadIdx.x;
    if (idx >= total4) return;
    int e  = idx << 2;                       // element base (multiple of 4)
    int hd = e & 127;
    int s  = (e / (nheads * HD)) & (SS - 1);
    int p0 = hd >> 1;
    float4 xv = ((const float4*)x)[idx];
    float4 cs = *(const float4*)(fc + ((size_t)(startpos[0] + s) * 64 + p0) * 2);
    float r0 = (xv.x * cs.x - xv.y * cs.y) * qscale;
    float r1 = (xv.x * cs.y + xv.y * cs.x) * qscale;
    float r2 = (xv.z * cs.z - xv.w * cs.w) * qscale;
    float r3 = (xv.z * cs.w + xv.w * cs.z) * qscale;
    __nv_bfloat16 h[4], l[4];
    float rr[4] = {r0, r1, r2, r3};
#pragma unroll
    for (int i = 0; i < 4; i++) {
        h[i] = __float2bfloat16(rr[i]);
        l[i] = __float2bfloat16(rr[i] - __bfloat162float(h[i]));
    }
    *(uint2*)(oh + e) = *(uint2*)h;
    *(uint2*)(ol + e) = *(uint2*)l;
}

// plain hi/lo split for v
__global__ void vsplit_kernel(const float* __restrict__ x,
                              __nv_bfloat16* __restrict__ oh,
                              __nv_bfloat16* __restrict__ ol, int total4)
{
    int idx = blockIdx.x * blockDim.x + threadIdx.x;
    if (idx >= total4) return;
    int e = idx << 2;
    float4 xv = ((const float4*)x)[idx];
    float rr[4] = {xv.x, xv.y, xv.z, xv.w};
    __nv_bfloat16 h[4], l[4];
#pragma unroll
    for (int i = 0; i < 4; i++) {
        h[i] = __float2bfloat16(rr[i]);
        l[i] = __float2bfloat16(rr[i] - __bfloat162float(h[i]));
    }
    *(uint2*)(oh + e) = *(uint2*)h;
    *(uint2*)(ol + e) = *(uint2*)l;
}

// ---------------------------------------------------------------------------
// bf16 MMA GEMM (projections): C[M,N] = A[M,K3] @ B[N,K3]^T + bias  (from R3)
// ---------------------------------------------------------------------------
#define CTM   128
#define CTN   128
#define GBK   32
#define NST   4
#define NCH   (K3 / GBK)
#define ROWB  80
#define ATILE (CTM * ROWB)
#define BTILE (CTN * ROWB)
#define STAGE (ATILE + BTILE)
#define GSMEM (NST * STAGE)

__global__ __launch_bounds__(256, 2) void gemm_mma(
    const __nv_bfloat16* __restrict__ A, const __nv_bfloat16* __restrict__ B,
    const float* __restrict__ bias, float* __restrict__ C, int N)
{
    extern __shared__ char smraw[];
    const int t    = threadIdx.x;
    const int lane = t & 31;
    const int wid  = t >> 5;
    const int wm   = wid & 1;
    const int wn   = wid >> 1;
    const int m0   = blockIdx.x * CTM;
    const int n0   = blockIdx.y * CTN;
    const uint32_t sb = smem_u32(smraw);

    float acc[4][4][4];
#pragma unroll
    for (int i = 0; i < 4; i++)
#pragma unroll
        for (int j = 0; j < 4; j++)
#pragma unroll
            for (int r = 0; r < 4; r++) acc[i][j][r] = 0.f;

    const __nv_bfloat16* Ag0 = A + (size_t)(m0 + (t >> 2)) * K3 + (t & 3) * 8;
    const __nv_bfloat16* Ag1 = A + (size_t)(m0 + ((t + 256) >> 2)) * K3 + (t & 3) * 8;
    const __nv_bfloat16* Bg0 = B + (size_t)(n0 + (t >> 2)) * K3 + (t & 3) * 8;
    const __nv_bfloat16* Bg1 = B + (size_t)(n0 + ((t + 256) >> 2)) * K3 + (t & 3) * 8;
    const uint32_t sA0 = (t >> 2) * ROWB + (t & 3) * 16;
    const uint32_t sA1 = ((t + 256) >> 2) * ROWB + (t & 3) * 16;

#define LOAD_STAGE(st, k0) do {                                        \
    uint32_t ab = sb + (st) * STAGE;                                   \
    uint32_t bb = ab + ATILE;                                          \
    CP_ASYNC16(ab + sA0, Ag0 + (k0));                                  \
    CP_ASYNC16(ab + sA1, Ag1 + (k0));                                  \
    CP_ASYNC16(bb + sA0, Bg0 + (k0));                                  \
    CP_ASYNC16(bb + sA1, Bg1 + (k0));                                  \
} while (0)

#pragma unroll
    for (int s = 0; s < NST - 1; s++) {
        LOAD_STAGE(s, s * GBK);
        CP_COMMIT();
    }

    const uint32_t aoffs = (wm * 64 + (lane & 15)) * ROWB + ((lane >> 4) << 4);
    const uint32_t boffs = (wn * 32 + (lane & 15)) * ROWB + ((lane >> 4) << 4);

    for (int c = 0; c < NCH; c++) {
        const int st = c & (NST - 1);
        CP_WAIT(2);
        __syncthreads();
        if (c + NST - 1 < NCH) LOAD_STAGE((c + NST - 1) & (NST - 1), (c + NST - 1) * GBK);
        CP_COMMIT();

        const uint32_t ab = sb + st * STAGE;
        const uint32_t bb = ab + ATILE;

#pragma unroll
        for (int ks = 0; ks < 2; ks++) {
            uint32_t a[4][4];
            uint32_t bf[4][2];
#pragma unroll
            for (int mi = 0; mi < 4; mi++)
                LDM_X4(a[mi][0], a[mi][1], a[mi][2], a[mi][3],
                       ab + aoffs + mi * 16 * ROWB + ks * 32);
#pragma unroll
            for (int p = 0; p < 2; p++) {
                uint32_t r0, r1, r2, r3;
                LDM_X4(r0, r1, r2, r3, bb + boffs + p * 16 * ROWB + ks * 32);
                bf[2*p][0]   = r0; bf[2*p][1]   = r2;
                bf[2*p+1][0] = r1; bf[2*p+1][1] = r3;
            }
#pragma unroll
            for (int mi = 0; mi < 4; mi++)
#pragma unroll
                for (int ni = 0; ni < 4; ni++)
                    MMA16816(acc[mi][ni], a[mi], bf[ni]);
        }
    }

#pragma unroll
    for (int mi = 0; mi < 4; mi++) {
        int r0 = m0 + wm * 64 + mi * 16 + (lane >> 2);
#pragma unroll
        for (int ni = 0; ni < 4; ni++) {
            int col = n0 + wn * 32 + ni * 8 + (lane & 3) * 2;
            float2 bv = *(const float2*)(bias + col);
            float2 o0 = make_float2(acc[mi][ni][0] + bv.x, acc[mi][ni][1] + bv.y);
            float2 o1 = make_float2(acc[mi][ni][2] + bv.x, acc[mi][ni][3] + bv.y);
            *(float2*)(C + (size_t)r0 * N + col)       = o0;
            *(float2*)(C + (size_t)(r0 + 8) * N + col) = o1;
        }
    }
#undef LOAD_STAGE
}

// ---------------------------------------------------------------------------
// Tensor-core causal flash attention.
// CTA: 128 q-rows x 64-key tiles. 8 warps, 16 rows each. 3-term bf16 splits.
// smem: Qh,Ql [128][128] + 2 stages of {Kh,Kl,Vh,Vl}[64][128], 272B row stride.
// ---------------------------------------------------------------------------
#define AROW     272
#define SQ_SZ    (128 * AROW)          // 34816
#define KT_SZ    (64 * AROW)           // 17408
#define STG_KH   0
#define STG_KL   17408
#define STG_VH   34816
#define STG_VL   52224
#define STG_SZ   (4 * KT_SZ)           // 69632
#define ATT_SMEM (2 * SQ_SZ + 2 * STG_SZ)   // 208896

__device__ __forceinline__ void att_load_kv(
    uint32_t dst, const __nv_bfloat16* khb, const __nv_bfloat16* klb,
    const __nv_bfloat16* vhb, const __nv_bfloat16* vlb, int n0, int t)
{
#pragma unroll
    for (int i = 0; i < 4; ++i) {
        int id = t + i * 256;
        int r  = id >> 4, c = id & 15;
        uint32_t o  = r * AROW + c * 16;
        size_t   go = (size_t)(n0 + r) * (KVH*HD) + c * 8;
        CP_ASYNC16(dst + STG_KH + o, khb + go);
        CP_ASYNC16(dst + STG_KL + o, klb + go);
        CP_ASYNC16(dst + STG_VH + o, vhb + go);
        CP_ASYNC16(dst + STG_VL + o, vlb + go);
    }
}

__global__ __launch_bounds__(256, 1) void attn_mma(
    const __nv_bfloat16* __restrict__ qh, const __nv_bfloat16* __restrict__ ql,
    const __nv_bfloat16* __restrict__ kh, const __nv_bfloat16* __restrict__ kl,
    const __nv_bfloat16* __restrict__ vh, const __nv_bfloat16* __restrict__ vl,
    __nv_bfloat16* __restrict__ cc)
{
    extern __shared__ char sm[];
    const int b   = blockIdx.z;
    const int h   = blockIdx.y;
    const int mb  = gridDim.x - 1 - blockIdx.x;     // heavy blocks first
    const int m0  = mb * 128;
    const int kvh = h / GROUP;
    const int t    = threadIdx.x;
    const int lane = t & 31;
    const int w    = t >> 5;

    const uint32_t sb   = smem_u32(sm);
    const uint32_t sQh  = sb;
    const uint32_t sQl  = sb + SQ_SZ;
    const uint32_t sStg = sb + 2 * SQ_SZ;

    const __nv_bfloat16* qhb = qh + ((size_t)(b*SS + m0) * QH + h) * HD;
    const __nv_bfloat16* qlb = ql + ((size_t)(b*SS + m0) * QH + h) * HD;
    const __nv_bfloat16* khb = kh + ((size_t)b*SS*KVH + kvh) * HD;
    const __nv_bfloat16* klb = kl + ((size_t)b*SS*KVH + kvh) * HD;
    const __nv_bfloat16* vhb = vh + ((size_t)b*SS*KVH + kvh) * HD;
    const __nv_bfloat16* vlb = vl + ((size_t)b*SS*KVH + kvh) * HD;

    // Q load (group 0 together with stage0)
#pragma unroll
    for (int i = 0; i < 8; ++i) {
        int id = t + i * 256;
        int r  = id >> 4, c = id & 15;
        uint32_t o  = r * AROW + c * 16;
        size_t   go = (size_t)r * (QH*HD) + c * 8;
        CP_ASYNC16(sQh + o, qhb + go);
        CP_ASYNC16(sQl + o, qlb + go);
    }
    att_load_kv(sStg, khb, klb, vhb, vlb, 0, t);
    CP_COMMIT();
    const int ntiles = 2 * mb + 2;
    if (ntiles > 1) att_load_kv(sStg + STG_SZ, khb, klb, vhb, vlb, 64, t);
    CP_COMMIT();

    // fragment offsets
    const uint32_t qoff = (w * 16 + (lane & 15)) * AROW + ((lane >> 4) << 4);
    const uint32_t koff = (lane & 15) * AROW + ((lane >> 4) << 4);
    const int vrow = (lane & 7) + ((lane >> 4) << 3);
    const uint32_t vcol = ((lane >> 3) & 1) << 4;

    float O[16][4];
#pragma unroll
    for (int i = 0; i < 16; i++)
#pragma unroll
        for (int j = 0; j < 4; j++) O[i][j] = 0.f;
    float mx0 = -INFINITY, mx1 = -INFINITY, l0 = 0.f, l1 = 0.f;

    const int row0 = m0 + w * 16 + (lane >> 2);
    const int row1 = row0 + 8;
    const int wrow_hi = m0 + w * 16 + 15;
    const int wrow_lo = m0 + w * 16;

    for (int it = 0; it < ntiles; ++it) {
        const int n0 = it * 64;
        CP_WAIT(1);
        __syncthreads();
        const uint32_t stg = sStg + (it & 1) * STG_SZ;

        if (n0 <= wrow_hi) {   // warp has unmasked rows in this tile
            float S[8][4];
#pragma unroll
            for (int i = 0; i < 8; i++)
#pragma unroll
                for (int j = 0; j < 4; j++) S[i][j] = 0.f;

            // ---- S = Qh*Kh + Ql*Kh + Qh*Kl ----
#pragma unroll
            for (int ch = 0; ch < 8; ++ch) {
                uint32_t aq[4], al[4];
                LDM_X4(aq[0], aq[1], aq[2], aq[3], sQh + qoff + ch * 32);
                LDM_X4(al[0], al[1], al[2], al[3], sQl + qoff + ch * 32);
#pragma unroll
                for (int p = 0; p < 4; ++p) {
                    uint32_t h0,h1,h2,h3, e0,e1,e2,e3;
                    LDM_X4(h0,h1,h2,h3, stg + STG_KH + koff + p*(16*AROW) + ch*32);
                    LDM_X4(e0,e1,e2,e3, stg + STG_KL + koff + p*(16*AROW) + ch*32);
                    uint32_t bh0[2] = {h0, h2}, bh1[2] = {h1, h3};
                    uint32_t bl0[2] = {e0, e2}, bl1[2] = {e1, e3};
                    MMA16816(S[2*p],   aq, bh0);
                    MMA16816(S[2*p+1], aq, bh1);
                    MMA16816(S[2*p],   al, bh0);
                    MMA16816(S[2*p+1], al, bh1);
                    MMA16816(S[2*p],   aq, bl0);
                    MMA16816(S[2*p+1], aq, bl1);
                }
            }

            // ---- causal mask ----
            if (n0 + 63 > wrow_lo) {
#pragma unroll
                for (int p = 0; p < 8; ++p) {
                    int c = n0 + p * 8 + (lane & 3) * 2;
                    if (c     > row0) S[p][0] = -INFINITY;
                    if (c + 1 > row0) S[p][1] = -INFINITY;
                    if (c     > row1) S[p][2] = -INFINITY;
                    if (c + 1 > row1) S[p][3] = -INFINITY;
                }
            }

            // ---- online softmax (log2 domain; scale folded into q) ----
            float t0 = -INFINITY, t1 = -INFINITY;
#pragma unroll
            for (int p = 0; p < 8; ++p) {
                t0 = fmaxf(t0, fmaxf(S[p][0], S[p][1]));
                t1 = fmaxf(t1, fmaxf(S[p][2], S[p][3]));
            }
            t0 = fmaxf(t0, __shfl_xor_sync(0xffffffffu, t0, 1));
            t0 = fmaxf(t0, __shfl_xor_sync(0xffffffffu, t0, 2));
            t1 = fmaxf(t1, __shfl_xor_sync(0xffffffffu, t1, 1));
            t1 = fmaxf(t1, __shfl_xor_sync(0xffffffffu, t1, 2));
            float mn0 = fmaxf(mx0, t0), mn1 = fmaxf(mx1, t1);
            float cr0 = ex2f(mx0 - mn0), cr1 = ex2f(mx1 - mn1);
            mx0 = mn0; mx1 = mn1;

            float sa0 = 0.f, sa1 = 0.f;
#pragma unroll
            for (int p = 0; p < 8; ++p) {
                S[p][0] = ex2f(S[p][0] - mn0);
                S[p][1] = ex2f(S[p][1] - mn0);
                S[p][2] = ex2f(S[p][2] - mn1);
                S[p][3] = ex2f(S[p][3] - mn1);
                sa0 += S[p][0] + S[p][1];
                sa1 += S[p][2] + S[p][3];
            }
            sa0 += __shfl_xor_sync(0xffffffffu, sa0, 1);
            sa0 += __shfl_xor_sync(0xffffffffu, sa0, 2);
            sa1 += __shfl_xor_sync(0xffffffffu, sa1, 1);
            sa1 += __shfl_xor_sync(0xffffffffu, sa1, 2);
            l0 = l0 * cr0 + sa0;
            l1 = l1 * cr1 + sa1;

#pragma unroll
            for (int i = 0; i < 16; i++) {
                O[i][0] *= cr0; O[i][1] *= cr0;
                O[i][2] *= cr1; O[i][3] *= cr1;
            }

            // ---- O += Ph*Vh + Pl*Vh + Ph*Vl ----
#pragma unroll
            for (int jc = 0; jc < 4; ++jc) {
                uint32_t ph[4], pl[4];
#pragma unroll
                for (int q2 = 0; q2 < 2; ++q2) {
                    float p0 = S[2*jc + q2][0], p1 = S[2*jc + q2][1];
                    float p2 = S[2*jc + q2][2], p3 = S[2*jc + q2][3];
                    uint32_t hp0 = pack_bf16(p0, p1);
                    uint32_t hp1 = pack_bf16(p2, p3);
                    float f0 = __uint_as_float(hp0 << 16);
                    float f1 = __uint_as_float(hp0 & 0xffff0000u);
                    float f2 = __uint_as_float(hp1 << 16);
                    float f3 = __uint_as_float(hp1 & 0xffff0000u);
                    ph[2*q2]   = hp0;  ph[2*q2+1] = hp1;
                    pl[2*q2]   = pack_bf16(p0 - f0, p1 - f1);
                    pl[2*q2+1] = pack_bf16(p2 - f2, p3 - f3);
                }
                const uint32_t vro = (jc * 16 + vrow) * AROW + vcol;
#pragma unroll
                for (int db = 0; db < 8; ++db) {
                    uint32_t a0,a1,a2,a3, c0,c1,c2,c3;
                    LDM_X4T(a0,a1,a2,a3, stg + STG_VH + vro + db * 32);
                    LDM_X4T(c0,c1,c2,c3, stg + STG_VL + vro + db * 32);
                    uint32_t bh0[2] = {a0, a2}, bh1[2] = {a1, a3};
                    uint32_t bl0[2] = {c0, c2}, bl1[2] = {c1, c3};
                    MMA16816(O[2*db],   ph, bh0);
                    MMA16816(O[2*db+1], ph, bh1);
                    MMA16816(O[2*db],   pl, bh0);
                    MMA16816(O[2*db+1], pl, bh1);
                    MMA16816(O[2*db],   ph, bl0);
                    MMA16816(O[2*db+1], ph, bl1);
                }
            }
        }

        __syncthreads();
        if (it + 2 < ntiles)
            att_load_kv(sStg + (it & 1) * STG_SZ, khb, klb, vhb, vlb, n0 + 128, t);
        CP_COMMIT();
    }

    // ---- normalize + 3-term split write to cc (A-form [hi|lo|hi]) ----
    float inv0 = 1.0f / l0, inv1 = 1.0f / l1;
    const size_t base0 = (size_t)(b * SS + row0) * K3;
    const size_t base1 = (size_t)(b * SS + row1) * K3;
    const int colb = h * 128 + (lane & 3) * 2;
#pragma unroll
    for (int dt = 0; dt < 16; ++dt) {
        int col = colb + dt * 8;
        float v0 = O[dt][0] * inv0, v1 = O[dt][1] * inv0;
        float v2 = O[dt][2] * inv1, v3 = O[dt][3] * inv1;
        uint32_t hi0 = pack_bf16(v0, v1);
        uint32_t hi1 = pack_bf16(v2, v3);
        float f0 = __uint_as_float(hi0 << 16), f1 = __uint_as_float(hi0 & 0xffff0000u);
        float f2 = __uint_as_float(hi1 << 16), f3 = __uint_as_float(hi1 & 0xffff0000u);
        uint32_t lo0 = pack_bf16(v0 - f0, v1 - f1);
        uint32_t lo1 = pack_bf16(v2 - f2, v3 - f3);
        *(uint32_t*)(cc + base0 + col)            = hi0;
        *(uint32_t*)(cc + base0 + DD + col)       = lo0;
        *(uint32_t*)(cc + base0 + 2*DD + col)     = hi0;
        *(uint32_t*)(cc + base1 + col)            = hi1;
        *(uint32_t*)(cc + base1 + DD + col)       = lo1;
        *(uint32_t*)(cc + base1 + 2*DD + col)     = hi1;
    }
}

// ---------------------------------------------------------------------------
// launch
// ---------------------------------------------------------------------------
extern "C" void kernel_launch(void* const* d_in, const int* in_sizes, int n_in,
                              void* d_out, int out_size)
{
    const float* xs   = (const float*)d_in[0];
    const int*   spos = (const int*)  d_in[1];
    const float* fc   = (const float*)d_in[2];
    const float* Wq   = (const float*)d_in[3];
    const float* bq   = (const float*)d_in[4];
    const float* Wk   = (const float*)d_in[5];
    const float* bk   = (const float*)d_in[6];
    const float* Wv   = (const float*)d_in[7];
    const float* bv   = (const float*)d_in[8];
    const float* Wo   = (const float*)d_in[9];
    const float* bo   = (const float*)d_in[10];
    float* out = (float*)d_out;

    float *qp, *kp, *vp;
    __nv_bfloat16 *xc, *wqc, *wkc, *wvc, *woc, *cc;
    __nv_bfloat16 *qhp, *qlp, *khp, *klp, *vhp, *vlp;
    cudaGetSymbolAddress((void**)&qp,  g_q);
    cudaGetSymbolAddress((void**)&kp,  g_k);
    cudaGetSymbolAddress((void**)&vp,  g_v);
    cudaGetSymbolAddress((void**)&xc,  g_xc);
    cudaGetSymbolAddress((void**)&wqc, g_wqc);
    cudaGetSymbolAddress((void**)&wkc, g_wkc);
    cudaGetSymbolAddress((void**)&wvc, g_wvc);
    cudaGetSymbolAddress((void**)&woc, g_woc);
    cudaGetSymbolAddress((void**)&cc,  g_cc);
    cudaGetSymbolAddress((void**)&qhp, g_qh);
    cudaGetSymbolAddress((void**)&qlp, g_ql);
    cudaGetSymbolAddress((void**)&khp, g_kh);
    cudaGetSymbolAddress((void**)&klp, g_kl);
    cudaGetSymbolAddress((void**)&vhp, g_vh);
    cudaGetSymbolAddress((void**)&vlp, g_vl);

    cudaFuncSetAttribute(gemm_mma, cudaFuncAttributeMaxDynamicSharedMemorySize, GSMEM);
    cudaFuncSetAttribute(attn_mma, cudaFuncAttributeMaxDynamicSharedMemorySize, ATT_SMEM);

    // split fp32 -> 3-term bf16 for projection inputs
    {
        int n;
        n = TOK*DD/4;  split_bf16_kernel<<<(n+255)/256, 256>>>(xs, xc,  DD, n, 0);
        n = DD*DD/4;   split_bf16_kernel<<<(n+255)/256, 256>>>(Wq, wqc, DD, n, 1);
        n = KVD*DD/4;  split_bf16_kernel<<<(n+255)/256, 256>>>(Wk, wkc, DD, n, 1);
        n = KVD*DD/4;  split_bf16_kernel<<<(n+255)/256, 256>>>(Wv, wvc, DD, n, 1);
        n = DD*DD/4;   split_bf16_kernel<<<(n+255)/256, 256>>>(Wo, woc, DD, n, 1);
    }

    // QKV projections
    gemm_mma<<<dim3(TOK/CTM, DD/CTN),  256, GSMEM>>>(xc, wqc, bq, qp, DD);
    gemm_mma<<<dim3(TOK/CTM, KVD/CTN), 256, GSMEM>>>(xc, wkc, bk, kp, KVD);
    gemm_mma<<<dim3(TOK/CTM, KVD/CTN), 256, GSMEM>>>(xc, wvc, bv, vp, KVD);

    // rope + split (scale*log2e folded into q)
    {
        const float qsc = 0.08838834764831845f * 1.4426950408889634f;
        int nq = TOK * DD / 4;
        int nk = TOK * KVD / 4;
        ropesplit_kernel<<<(nq+255)/256, 256>>>(qp, fc, spos, qhp, qlp, QH,  nq, qsc);
        ropesplit_kernel<<<(nk+255)/256, 256>>>(kp, fc, spos, khp, klp, KVH, nk, 1.0f);
        vsplit_kernel<<<(nk+255)/256, 256>>>(vp, vhp, vlp, nk);
    }

    // tensor-core flash attention -> cc (3-term split, A-form)
    attn_mma<<<dim3(SS/128, QH, BB), 256, ATT_SMEM>>>(qhp, qlp, khp, klp, vhp, vlp, cc);

    // output projection
    gemm_mma<<<dim3(TOK/CTM, DD/CTN), 256, GSMEM>>>(cc, woc, bo, out, DD);
}